// round 1
// baseline (speedup 1.0000x reference)
#include <cuda_runtime.h>
#include <math.h>

// ---------------- constants ----------------
#define Bn 32
#define Hdim 64
#define Wdim 64
#define Cdim 256
#define NHn 8
#define WSn 8
#define SHIFTn 4
#define HDn 32            // C/NH
#define Nn_tok 64         // WS*WS
#define NWn 64            // (H/WS)*(W/WS)
#define HIDn 1024
#define NTOK 131072       // B*NW*N = B*H*W
#define LOGIT_MAX 4.6051702f

// ---------------- scratch (device globals; no runtime alloc) ----------------
__device__ float g_q[33554432];        // [2048][8][64][32]
__device__ float g_k[33554432];
__device__ float g_v[33554432];
__device__ float g_attnout[33554432];  // windowed [t][C]
__device__ float g_projout[33554432];  // natural  [p][C]
__device__ float g_x1[33554432];       // natural  [p][C]
__device__ float g_h[134217728];       // [t][1024]
__device__ float g_h2[33554432];       // [t][256]
__device__ float g_tbl[225 * 8];       // CPB table

// ---------------- CPB MLP table ----------------
__global__ void cpb_kernel(const float* __restrict__ w1, const float* __restrict__ b1,
                           const float* __restrict__ w2) {
    int idx = blockIdx.x;            // 0..224
    int i = idx / 15, j = idx % 15;
    float a0 = (float)(i - 7) * (8.0f / 7.0f);
    float a1 = (float)(j - 7) * (8.0f / 7.0f);
    float r0 = copysignf(log2f(fabsf(a0) + 1.0f) * (1.0f / 3.0f), a0);
    float r1 = copysignf(log2f(fabsf(a1) + 1.0f) * (1.0f / 3.0f), a1);
    float acc[8];
#pragma unroll
    for (int h = 0; h < 8; h++) acc[h] = 0.0f;
    for (int jj = threadIdx.x; jj < 512; jj += 256) {
        float hv = fmaxf(fmaf(r0, w1[jj], fmaf(r1, w1[512 + jj], b1[jj])), 0.0f);
#pragma unroll
        for (int h = 0; h < 8; h++) acc[h] += hv * w2[jj * 8 + h];
    }
    __shared__ float red[256][8];
#pragma unroll
    for (int h = 0; h < 8; h++) red[threadIdx.x][h] = acc[h];
    __syncthreads();
    for (int s = 128; s > 0; s >>= 1) {
        if (threadIdx.x < s) {
#pragma unroll
            for (int h = 0; h < 8; h++) red[threadIdx.x][h] += red[threadIdx.x + s][h];
        }
        __syncthreads();
    }
    if (threadIdx.x < 8) g_tbl[idx * 8 + threadIdx.x] = red[0][threadIdx.x];
}

// ---------------- generic tiled SGEMM with mode-specific gather/epilogue ----
// MODE 0: A = x (gather via shift+window), W=qkv_w (256x768), scatter q/k/v + biases
// MODE 1: A = g_attnout, W=proj_w (256x256), +proj_b, scatter to natural layout
// MODE 2: A = g_x1, W=fc1_w (256x1024), gelu(.+fc1_b) -> g_h
// MODE 3: A = g_h, W=fc2_w (1024x256), +fc2_b -> g_h2
template <int MODE>
__global__ void gemm_kernel(const float* __restrict__ Ain, const float* __restrict__ W,
                            const float* __restrict__ bias0, const float* __restrict__ bias1,
                            int Ncols, int K) {
    __shared__ __align__(16) float As[16][68];
    __shared__ __align__(16) float Bs[16][64];
    const float* A = (MODE == 0) ? Ain : (MODE == 1) ? g_attnout : (MODE == 2) ? g_x1 : g_h;

    int tid = threadIdx.x;
    int t0 = blockIdx.x * 64;
    int j0 = blockIdx.y * 64;
    int ka = tid & 15, ma = tid >> 4;   // A tile load role
    int nb = tid & 63, kb = tid >> 6;   // B tile load role

    const float* aptr[4];
#pragma unroll
    for (int i = 0; i < 4; i++) {
        int t = t0 + ma + i * 16;
        size_t row;
        if (MODE == 0) {
            int w = t >> 6, n = t & 63;
            int b = w >> 6, wi = w & 63;
            int wh = wi >> 3, ww = wi & 7;
            int r = n >> 3, c = n & 7;
            int oh = (wh * 8 + r + SHIFTn) & 63;
            int ow = (ww * 8 + c + SHIFTn) & 63;
            row = (size_t)(b * 4096 + oh * 64 + ow) * 256;
        } else {
            row = (size_t)t * (size_t)K;
        }
        aptr[i] = A + row + ka;
    }
    const float* bptr = W + (size_t)kb * Ncols + j0 + nb;

    float acc[4][4];
#pragma unroll
    for (int i = 0; i < 4; i++)
#pragma unroll
        for (int j = 0; j < 4; j++) acc[i][j] = 0.0f;

    int ty = tid >> 4, tx = tid & 15;
    for (int k0 = 0; k0 < K; k0 += 16) {
#pragma unroll
        for (int i = 0; i < 4; i++) As[ka][ma + i * 16] = aptr[i][k0];
#pragma unroll
        for (int i = 0; i < 4; i++) Bs[kb + i * 4][nb] = bptr[(size_t)(k0 + i * 4) * Ncols];
        __syncthreads();
#pragma unroll
        for (int kk = 0; kk < 16; kk++) {
            float4 av = *(const float4*)&As[kk][ty * 4];
            float4 bv = *(const float4*)&Bs[kk][tx * 4];
            float a4[4] = {av.x, av.y, av.z, av.w};
            float b4[4] = {bv.x, bv.y, bv.z, bv.w};
#pragma unroll
            for (int i = 0; i < 4; i++)
#pragma unroll
                for (int j = 0; j < 4; j++) acc[i][j] = fmaf(a4[i], b4[j], acc[i][j]);
        }
        __syncthreads();
    }

    // epilogue
#pragma unroll
    for (int i = 0; i < 4; i++) {
        int t = t0 + ty * 4 + i;
        int w = t >> 6, n = t & 63;
        size_t p_nat = 0;
        if (MODE == 1) {
            int b = w >> 6, wi = w & 63;
            int wh = wi >> 3, ww = wi & 7;
            int r = n >> 3, c = n & 7;
            int oh = (wh * 8 + r + SHIFTn) & 63;
            int ow = (ww * 8 + c + SHIFTn) & 63;
            p_nat = (size_t)(b * 4096 + oh * 64 + ow);
        }
#pragma unroll
        for (int j = 0; j < 4; j++) {
            int col = j0 + tx * 4 + j;
            float v = acc[i][j];
            if (MODE == 0) {
                int part = col >> 8;
                int hh = (col >> 5) & 7;
                int hd = col & 31;
                if (part == 0) v += bias0[col];
                else if (part == 2) v += bias1[col - 512];
                size_t dst = ((size_t)(w * 8 + hh) * 64 + n) * 32 + hd;
                if (part == 0) g_q[dst] = v;
                else if (part == 1) g_k[dst] = v;
                else g_v[dst] = v;
            } else if (MODE == 1) {
                v += bias0[col];
                g_projout[p_nat * 256 + col] = v;
            } else if (MODE == 2) {
                v += bias0[col];
                v = 0.5f * v * (1.0f + erff(v * 0.70710678118654752f));
                g_h[(size_t)t * 1024 + col] = v;
            } else {
                v += bias0[col];
                g_h2[(size_t)t * 256 + col] = v;
            }
        }
    }
}

// ---------------- windowed cosine attention ----------------
__global__ void attn_kernel(const float* __restrict__ logit_scale) {
    __shared__ __align__(16) float qT[32][68];  // [hd][n]
    __shared__ __align__(16) float kT[32][68];
    __shared__ __align__(16) float vS[64][32];  // [n][hd]
    __shared__ float S[64][65];
    __shared__ float qn[64], kn[64];
    __shared__ int rid[64];

    int w = blockIdx.x, h = blockIdx.y;
    int tid = threadIdx.x;
    size_t base = (size_t)(w * 8 + h) * 2048;

    for (int idx = tid; idx < 2048; idx += 256) {
        int n = idx >> 5, d = idx & 31;
        qT[d][n] = g_q[base + idx];
        kT[d][n] = g_k[base + idx];
        vS[n][d] = g_v[base + idx];
    }
    __syncthreads();

    if (tid < 64) {
        float s = 0.0f;
#pragma unroll
        for (int d = 0; d < 32; d++) s = fmaf(qT[d][tid], qT[d][tid], s);
        qn[tid] = rsqrtf(fmaxf(s, 1e-12f));
        int wi = w & 63;
        int wh = wi >> 3, ww = wi & 7;
        int r = tid >> 3, c = tid & 7;
        int sh = wh * 8 + r, sw = ww * 8 + c;
        int rr = sh < 56 ? 0 : (sh < 60 ? 1 : 2);
        int rc = sw < 56 ? 0 : (sw < 60 ? 1 : 2);
        rid[tid] = rr * 3 + rc;
    } else if (tid < 128) {
        int n = tid - 64;
        float s = 0.0f;
#pragma unroll
        for (int d = 0; d < 32; d++) s = fmaf(kT[d][n], kT[d][n], s);
        kn[n] = rsqrtf(fmaxf(s, 1e-12f));
    }
    __syncthreads();

    float sc = expf(fminf(logit_scale[h], LOGIT_MAX));
    int ty = tid >> 4, tx = tid & 15;
    float acc[4][4];
#pragma unroll
    for (int i = 0; i < 4; i++)
#pragma unroll
        for (int j = 0; j < 4; j++) acc[i][j] = 0.0f;

#pragma unroll
    for (int kk = 0; kk < 32; kk++) {
        float4 av = *(const float4*)&qT[kk][ty * 4];
        float4 bv = *(const float4*)&kT[kk][tx * 4];
        float a4[4] = {av.x, av.y, av.z, av.w};
        float b4[4] = {bv.x, bv.y, bv.z, bv.w};
#pragma unroll
        for (int i = 0; i < 4; i++)
#pragma unroll
            for (int j = 0; j < 4; j++) acc[i][j] = fmaf(a4[i], b4[j], acc[i][j]);
    }

#pragma unroll
    for (int i = 0; i < 4; i++) {
        int ri = ty * 4 + i;
#pragma unroll
        for (int j = 0; j < 4; j++) {
            int cj = tx * 4 + j;
            float val = acc[i][j] * qn[ri] * kn[cj] * sc;
            int rel = ((ri >> 3) - (cj >> 3) + 7) * 15 + ((ri & 7) - (cj & 7) + 7);
            float tb = g_tbl[rel * 8 + h];
            val += 16.0f / (1.0f + expf(-tb));
            if (rid[ri] != rid[cj]) val -= 100.0f;
            S[ri][cj] = val;
        }
    }
    __syncthreads();

    if (tid < 64) {
        float m = -1e30f;
#pragma unroll
        for (int j = 0; j < 64; j++) m = fmaxf(m, S[tid][j]);
        float s = 0.0f;
#pragma unroll
        for (int j = 0; j < 64; j++) {
            float e = expf(S[tid][j] - m);
            S[tid][j] = e;
            s += e;
        }
        float inv = 1.0f / s;
#pragma unroll
        for (int j = 0; j < 64; j++) S[tid][j] *= inv;
    }
    __syncthreads();

    int ty2 = tid >> 3, tx2 = tid & 7;  // rows {ty2, ty2+32}, cols tx2*4..+3
    float o0[4] = {0, 0, 0, 0}, o1[4] = {0, 0, 0, 0};
#pragma unroll
    for (int m = 0; m < 64; m++) {
        float p0 = S[ty2][m];
        float p1 = S[ty2 + 32][m];
        float4 vv = *(const float4*)&vS[m][tx2 * 4];
        float v4[4] = {vv.x, vv.y, vv.z, vv.w};
#pragma unroll
        for (int j = 0; j < 4; j++) {
            o0[j] = fmaf(p0, v4[j], o0[j]);
            o1[j] = fmaf(p1, v4[j], o1[j]);
        }
    }
    {
        size_t d0 = (size_t)(w * 64 + ty2) * 256 + h * 32 + tx2 * 4;
        size_t d1 = (size_t)(w * 64 + ty2 + 32) * 256 + h * 32 + tx2 * 4;
        float4 r0 = make_float4(o0[0], o0[1], o0[2], o0[3]);
        float4 r1 = make_float4(o1[0], o1[1], o1[2], o1[3]);
        *(float4*)&g_attnout[d0] = r0;
        *(float4*)&g_attnout[d1] = r1;
    }
}

// ---------------- LayerNorm + residual ----------------
// WHICH 0: g_x1 = base(x) + LN(g_projout)   WHICH 1: out = g_x1 + LN(g_h2)
template <int WHICH>
__global__ void ln_add_kernel(const float* __restrict__ basep,
                              const float* __restrict__ g, const float* __restrict__ b,
                              float* __restrict__ outp) {
    const float* base = (WHICH == 0) ? basep : g_x1;
    const float* y = (WHICH == 0) ? g_projout : g_h2;
    float* out = (WHICH == 0) ? g_x1 : outp;

    int t = blockIdx.x;
    int c = threadIdx.x;
    size_t off = (size_t)t * 256 + c;
    float v = y[off];
    float s = v, s2 = v * v;
#pragma unroll
    for (int o = 16; o > 0; o >>= 1) {
        s += __shfl_xor_sync(0xffffffffu, s, o);
        s2 += __shfl_xor_sync(0xffffffffu, s2, o);
    }
    __shared__ float rs[8], rs2[8];
    int wid = c >> 5, lid = c & 31;
    if (lid == 0) { rs[wid] = s; rs2[wid] = s2; }
    __syncthreads();
    if (wid == 0) {
        float a = (lid < 8) ? rs[lid] : 0.0f;
        float a2 = (lid < 8) ? rs2[lid] : 0.0f;
#pragma unroll
        for (int o = 4; o > 0; o >>= 1) {
            a += __shfl_xor_sync(0xffffffffu, a, o);
            a2 += __shfl_xor_sync(0xffffffffu, a2, o);
        }
        if (lid == 0) { rs[0] = a; rs2[0] = a2; }
    }
    __syncthreads();
    float mu = rs[0] * (1.0f / 256.0f);
    float var = rs2[0] * (1.0f / 256.0f) - mu * mu;
    float inv = rsqrtf(var + 1e-5f);
    out[off] = base[off] + (v - mu) * inv * g[c] + b[c];
}

// ---------------- launch ----------------
extern "C" void kernel_launch(void* const* d_in, const int* in_sizes, int n_in,
                              void* d_out, int out_size) {
    const float* x = (const float*)d_in[0];
    const float* qkv_w = (const float*)d_in[1];
    const float* q_bias = (const float*)d_in[2];
    const float* v_bias = (const float*)d_in[3];
    const float* logit_scale = (const float*)d_in[4];
    const float* cpb_w1 = (const float*)d_in[5];
    const float* cpb_b1 = (const float*)d_in[6];
    const float* cpb_w2 = (const float*)d_in[7];
    const float* proj_w = (const float*)d_in[8];
    const float* proj_b = (const float*)d_in[9];
    const float* norm1_g = (const float*)d_in[10];
    const float* norm1_b = (const float*)d_in[11];
    const float* fc1_w = (const float*)d_in[12];
    const float* fc1_b = (const float*)d_in[13];
    const float* fc2_w = (const float*)d_in[14];
    const float* fc2_b = (const float*)d_in[15];
    const float* norm2_g = (const float*)d_in[16];
    const float* norm2_b = (const float*)d_in[17];
    float* out = (float*)d_out;

    cpb_kernel<<<225, 256>>>(cpb_w1, cpb_b1, cpb_w2);

    // QKV: [131072,256] x [256,768]
    gemm_kernel<0><<<dim3(2048, 12), 256>>>(x, qkv_w, q_bias, v_bias, 768, 256);

    // attention per (window, head)
    attn_kernel<<<dim3(2048, 8), 256>>>(logit_scale);

    // proj: [131072,256] x [256,256], scatter to natural layout
    gemm_kernel<1><<<dim3(2048, 4), 256>>>(nullptr, proj_w, proj_b, nullptr, 256, 256);

    // x1 = x + LN(projout)
    ln_add_kernel<0><<<NTOK, 256>>>(x, norm1_g, norm1_b, nullptr);

    // fc1 + gelu: [131072,256] x [256,1024]
    gemm_kernel<2><<<dim3(2048, 16), 256>>>(nullptr, fc1_w, fc1_b, nullptr, 1024, 256);

    // fc2: [131072,1024] x [1024,256]
    gemm_kernel<3><<<dim3(2048, 4), 256>>>(nullptr, fc2_w, fc2_b, nullptr, 256, 1024);

    // out = x1 + LN(h2)
    ln_add_kernel<1><<<NTOK, 256>>>(nullptr, norm2_g, norm2_b, out);

    (void)in_sizes; (void)n_in; (void)out_size;
}

// round 2
// speedup vs baseline: 1.9723x; 1.9723x over previous
#include <cuda_runtime.h>
#include <math.h>

// ---------------- constants ----------------
#define SHIFTn 4
#define NTOK 131072
#define LOGIT_MAX 4.6051702f

// ---------------- scratch ----------------
__device__ float g_q[33554432];        // [2048][8][64][32]
__device__ float g_k[33554432];
__device__ float g_v[33554432];
__device__ float g_attnout[33554432];  // windowed [t][C]
__device__ float g_projout[33554432];  // natural  [p][C]
__device__ float g_x1[33554432];       // natural  [p][C]
__device__ float g_h[134217728];       // [t][1024]
__device__ float g_h2[33554432];       // [t][256]
__device__ float g_tbl[225 * 8];

// ---------------- helpers ----------------
__device__ __forceinline__ float cvt_tf32f(float x) {
    unsigned r;
    asm("cvt.rna.tf32.f32 %0, %1;" : "=r"(r) : "f"(x));
    return __uint_as_float(r);
}

__device__ __forceinline__ void mma_tf32(float* d, const unsigned* a, const unsigned* b) {
    asm volatile(
        "mma.sync.aligned.m16n8k8.row.col.f32.tf32.tf32.f32 "
        "{%0,%1,%2,%3},{%4,%5,%6,%7},{%8,%9},{%0,%1,%2,%3};"
        : "+f"(d[0]), "+f"(d[1]), "+f"(d[2]), "+f"(d[3])
        : "r"(a[0]), "r"(a[1]), "r"(a[2]), "r"(a[3]), "r"(b[0]), "r"(b[1]));
}

// ---------------- CPB MLP table ----------------
__global__ void cpb_kernel(const float* __restrict__ w1, const float* __restrict__ b1,
                           const float* __restrict__ w2) {
    int idx = blockIdx.x;
    int i = idx / 15, j = idx % 15;
    float a0 = (float)(i - 7) * (8.0f / 7.0f);
    float a1 = (float)(j - 7) * (8.0f / 7.0f);
    float r0 = copysignf(log2f(fabsf(a0) + 1.0f) * (1.0f / 3.0f), a0);
    float r1 = copysignf(log2f(fabsf(a1) + 1.0f) * (1.0f / 3.0f), a1);
    float acc[8];
#pragma unroll
    for (int h = 0; h < 8; h++) acc[h] = 0.0f;
    for (int jj = threadIdx.x; jj < 512; jj += 256) {
        float hv = fmaxf(fmaf(r0, w1[jj], fmaf(r1, w1[512 + jj], b1[jj])), 0.0f);
#pragma unroll
        for (int h = 0; h < 8; h++) acc[h] += hv * w2[jj * 8 + h];
    }
    __shared__ float red[256][8];
#pragma unroll
    for (int h = 0; h < 8; h++) red[threadIdx.x][h] = acc[h];
    __syncthreads();
    for (int s = 128; s > 0; s >>= 1) {
        if (threadIdx.x < s) {
#pragma unroll
            for (int h = 0; h < 8; h++) red[threadIdx.x][h] += red[threadIdx.x + s][h];
        }
        __syncthreads();
    }
    if (threadIdx.x < 8) g_tbl[idx * 8 + threadIdx.x] = red[0][threadIdx.x];
}

// ---------------- tf32 tensor-core GEMM ----------------
// BM=128, BN=128, BK=16. 8 warps, warp tile 32(M) x 64(N).
// MODE 0: A = x (shift+window gather), W=qkv_w, scatter q/k/v + biases
// MODE 1: A = g_attnout, W=proj_w, +proj_b, scatter to natural layout
// MODE 2: A = g_x1, W=fc1_w, gelu -> g_h
// MODE 3: A = g_h, W=fc2_w, +fc2_b -> g_h2
template <int MODE>
__global__ void __launch_bounds__(256, 2)
mma_gemm(const float* __restrict__ Ain, const float* __restrict__ W,
         const float* __restrict__ bias0, const float* __restrict__ bias1,
         int Ncols, int K) {
    __shared__ float As[2][16][136];        // [k][m'] fragment-permuted in m
    __shared__ float2 Bs[2][2][4][132];     // [kstep][k&3][n] : (B[k], B[k+4])

    const float* A = (MODE == 0) ? Ain : (MODE == 1) ? g_attnout : (MODE == 2) ? g_x1 : g_h;

    int tid = threadIdx.x;
    int lane = tid & 31, wid = tid >> 5;
    int wm = (wid & 3) * 32, wn = (wid >> 2) * 64;
    int t0 = blockIdx.x * 128, j0 = blockIdx.y * 128;

    // --- global load roles ---
    // A: rows m = tid>>2 and (tid>>2)+64; cols (tid&3)*4 .. +3
    int ma0 = tid >> 2, ma1 = ma0 + 64;
    int k4c = (tid & 3) * 4;
    const float* aptr[2];
#pragma unroll
    for (int i = 0; i < 2; i++) {
        int t = t0 + (i ? ma1 : ma0);
        size_t row;
        if (MODE == 0) {
            int w = t >> 6, n = t & 63;
            int b = w >> 6, wi = w & 63;
            int wh = wi >> 3, ww = wi & 7;
            int r = n >> 3, c = n & 7;
            int oh = (wh * 8 + r + SHIFTn) & 63;
            int ow = (ww * 8 + c + SHIFTn) & 63;
            row = (size_t)(b * 4096 + oh * 64 + ow) * 256;
        } else {
            row = (size_t)t * (size_t)K;
        }
        aptr[i] = A + row + k4c;
    }
    // B: rows kb = wid and wid+8; cols nb = lane*4
    int kb = wid, nb = lane * 4;
    const float* bptr = W + (size_t)kb * Ncols + j0 + nb;

    float acc[2][8][4];
#pragma unroll
    for (int mt = 0; mt < 2; mt++)
#pragma unroll
        for (int nt = 0; nt < 8; nt++)
#pragma unroll
            for (int i = 0; i < 4; i++) acc[mt][nt][i] = 0.0f;

    float4 la0, la1, lb0, lb1;
    // prologue load k0=0
    la0 = *(const float4*)(aptr[0]);
    la1 = *(const float4*)(aptr[1]);
    lb0 = *(const float4*)(bptr);
    lb1 = *(const float4*)(bptr + (size_t)8 * Ncols);

    int buf = 0;
    // store tile 0
    {
#pragma unroll
        for (int j = 0; j < 4; j++) {
            float av0 = cvt_tf32f(((const float*)&la0)[j]);
            float av1 = cvt_tf32f(((const float*)&la1)[j]);
            int mp0 = ((ma0 >> 4) << 4) | ((ma0 & 7) << 1) | ((ma0 >> 3) & 1);
            int mp1 = ((ma1 >> 4) << 4) | ((ma1 & 7) << 1) | ((ma1 >> 3) & 1);
            As[buf][k4c + j][mp0] = av0;
            As[buf][k4c + j][mp1] = av1;
            float bv0 = cvt_tf32f(((const float*)&lb0)[j]);
            float bv1 = cvt_tf32f(((const float*)&lb1)[j]);
            ((float*)&Bs[buf][0][kb & 3][nb + j])[(kb >> 2) & 1] = bv0;
            int k2 = kb + 8;
            ((float*)&Bs[buf][1][k2 & 3][nb + j])[(k2 >> 2) & 1] = bv1;
        }
    }
    __syncthreads();

    int r = lane & 3, q = lane >> 2;
    for (int k0 = 0; k0 < K; k0 += 16) {
        bool more = (k0 + 16) < K;
        if (more) {
            la0 = *(const float4*)(aptr[0] + k0 + 16);
            la1 = *(const float4*)(aptr[1] + k0 + 16);
            lb0 = *(const float4*)(bptr + (size_t)(k0 + 16) * Ncols);
            lb1 = *(const float4*)(bptr + (size_t)(k0 + 24) * Ncols);
        }
        // compute two k8 steps
#pragma unroll
        for (int s = 0; s < 2; s++) {
            unsigned afr[2][4];
#pragma unroll
            for (int mt = 0; mt < 2; mt++) {
                float2 p01 = *(const float2*)&As[buf][s * 8 + r][wm + mt * 16 + q * 2];
                float2 p23 = *(const float2*)&As[buf][s * 8 + 4 + r][wm + mt * 16 + q * 2];
                afr[mt][0] = __float_as_uint(p01.x);
                afr[mt][1] = __float_as_uint(p01.y);
                afr[mt][2] = __float_as_uint(p23.x);
                afr[mt][3] = __float_as_uint(p23.y);
            }
#pragma unroll
            for (int nt = 0; nt < 8; nt++) {
                float2 pb = Bs[buf][s][r][wn + nt * 8 + q];
                unsigned bfr[2] = {__float_as_uint(pb.x), __float_as_uint(pb.y)};
#pragma unroll
                for (int mt = 0; mt < 2; mt++) mma_tf32(acc[mt][nt], afr[mt], bfr);
            }
        }
        if (more) {
            int nb2 = buf ^ 1;
#pragma unroll
            for (int j = 0; j < 4; j++) {
                float av0 = cvt_tf32f(((const float*)&la0)[j]);
                float av1 = cvt_tf32f(((const float*)&la1)[j]);
                int mp0 = ((ma0 >> 4) << 4) | ((ma0 & 7) << 1) | ((ma0 >> 3) & 1);
                int mp1 = ((ma1 >> 4) << 4) | ((ma1 & 7) << 1) | ((ma1 >> 3) & 1);
                As[nb2][k4c + j][mp0] = av0;
                As[nb2][k4c + j][mp1] = av1;
                float bv0 = cvt_tf32f(((const float*)&lb0)[j]);
                float bv1 = cvt_tf32f(((const float*)&lb1)[j]);
                ((float*)&Bs[nb2][0][kb & 3][nb + j])[(kb >> 2) & 1] = bv0;
                int k2 = kb + 8;
                ((float*)&Bs[nb2][1][k2 & 3][nb + j])[(k2 >> 2) & 1] = bv1;
            }
            __syncthreads();
            buf = nb2;
        }
    }

    // ---------------- epilogue ----------------
#pragma unroll
    for (int mt = 0; mt < 2; mt++) {
#pragma unroll
        for (int i2 = 0; i2 < 2; i2++) {  // row half (i>>1)
            int row = wm + mt * 16 + (lane >> 2) + 8 * i2;
            int t = t0 + row;
            int w = t >> 6, n = t & 63;
            size_t p_nat = 0;
            if (MODE == 1) {
                int b = w >> 6, wi = w & 63;
                int wh = wi >> 3, ww = wi & 7;
                int rr = n >> 3, cc = n & 7;
                int oh = (wh * 8 + rr + SHIFTn) & 63;
                int ow = (ww * 8 + cc + SHIFTn) & 63;
                p_nat = (size_t)(b * 4096 + oh * 64 + ow);
            }
#pragma unroll
            for (int nt = 0; nt < 8; nt++) {
#pragma unroll
                for (int j = 0; j < 2; j++) {
                    int col = j0 + wn + nt * 8 + (lane & 3) * 2 + j;
                    float v = acc[mt][nt][i2 * 2 + j];
                    if (MODE == 0) {
                        int part = col >> 8;
                        int hh = (col >> 5) & 7;
                        int hd = col & 31;
                        if (part == 0) v += bias0[col];
                        else if (part == 2) v += bias1[col - 512];
                        size_t dst = ((size_t)(w * 8 + hh) * 64 + n) * 32 + hd;
                        if (part == 0) g_q[dst] = v;
                        else if (part == 1) g_k[dst] = v;
                        else g_v[dst] = v;
                    } else if (MODE == 1) {
                        v += bias0[col];
                        g_projout[p_nat * 256 + col] = v;
                    } else if (MODE == 2) {
                        v += bias0[col];
                        v = 0.5f * v * (1.0f + erff(v * 0.70710678118654752f));
                        g_h[(size_t)t * 1024 + col] = v;
                    } else {
                        v += bias0[col];
                        g_h2[(size_t)t * 256 + col] = v;
                    }
                }
            }
        }
    }
}

// ---------------- windowed cosine attention ----------------
__global__ void attn_kernel(const float* __restrict__ logit_scale) {
    __shared__ __align__(16) float qT[32][68];
    __shared__ __align__(16) float kT[32][68];
    __shared__ __align__(16) float vS[64][32];
    __shared__ float S[64][65];
    __shared__ float qn[64], kn[64];
    __shared__ int rid[64];

    int w = blockIdx.x, h = blockIdx.y;
    int tid = threadIdx.x;
    size_t base = (size_t)(w * 8 + h) * 2048;

    for (int idx = tid; idx < 2048; idx += 256) {
        int n = idx >> 5, d = idx & 31;
        qT[d][n] = g_q[base + idx];
        kT[d][n] = g_k[base + idx];
        vS[n][d] = g_v[base + idx];
    }
    __syncthreads();

    if (tid < 64) {
        float s = 0.0f;
#pragma unroll
        for (int d = 0; d < 32; d++) s = fmaf(qT[d][tid], qT[d][tid], s);
        qn[tid] = rsqrtf(fmaxf(s, 1e-12f));
        int wi = w & 63;
        int wh = wi >> 3, ww = wi & 7;
        int r = tid >> 3, c = tid & 7;
        int sh = wh * 8 + r, sw = ww * 8 + c;
        int rr = sh < 56 ? 0 : (sh < 60 ? 1 : 2);
        int rc = sw < 56 ? 0 : (sw < 60 ? 1 : 2);
        rid[tid] = rr * 3 + rc;
    } else if (tid < 128) {
        int n = tid - 64;
        float s = 0.0f;
#pragma unroll
        for (int d = 0; d < 32; d++) s = fmaf(kT[d][n], kT[d][n], s);
        kn[n] = rsqrtf(fmaxf(s, 1e-12f));
    }
    __syncthreads();

    float sc = expf(fminf(logit_scale[h], LOGIT_MAX));
    int ty = tid >> 4, tx = tid & 15;
    float acc[4][4];
#pragma unroll
    for (int i = 0; i < 4; i++)
#pragma unroll
        for (int j = 0; j < 4; j++) acc[i][j] = 0.0f;

#pragma unroll
    for (int kk = 0; kk < 32; kk++) {
        float4 av = *(const float4*)&qT[kk][ty * 4];
        float4 bv = *(const float4*)&kT[kk][tx * 4];
        float a4[4] = {av.x, av.y, av.z, av.w};
        float b4[4] = {bv.x, bv.y, bv.z, bv.w};
#pragma unroll
        for (int i = 0; i < 4; i++)
#pragma unroll
            for (int j = 0; j < 4; j++) acc[i][j] = fmaf(a4[i], b4[j], acc[i][j]);
    }

#pragma unroll
    for (int i = 0; i < 4; i++) {
        int ri = ty * 4 + i;
#pragma unroll
        for (int j = 0; j < 4; j++) {
            int cj = tx * 4 + j;
            float val = acc[i][j] * qn[ri] * kn[cj] * sc;
            int rel = ((ri >> 3) - (cj >> 3) + 7) * 15 + ((ri & 7) - (cj & 7) + 7);
            float tb = g_tbl[rel * 8 + h];
            val += 16.0f / (1.0f + expf(-tb));
            if (rid[ri] != rid[cj]) val -= 100.0f;
            S[ri][cj] = val;
        }
    }
    __syncthreads();

    if (tid < 64) {
        float m = -1e30f;
#pragma unroll
        for (int j = 0; j < 64; j++) m = fmaxf(m, S[tid][j]);
        float s = 0.0f;
#pragma unroll
        for (int j = 0; j < 64; j++) {
            float e = expf(S[tid][j] - m);
            S[tid][j] = e;
            s += e;
        }
        float inv = 1.0f / s;
#pragma unroll
        for (int j = 0; j < 64; j++) S[tid][j] *= inv;
    }
    __syncthreads();

    int ty2 = tid >> 3, tx2 = tid & 7;
    float o0[4] = {0, 0, 0, 0}, o1[4] = {0, 0, 0, 0};
#pragma unroll
    for (int m = 0; m < 64; m++) {
        float p0 = S[ty2][m];
        float p1 = S[ty2 + 32][m];
        float4 vv = *(const float4*)&vS[m][tx2 * 4];
        float v4[4] = {vv.x, vv.y, vv.z, vv.w};
#pragma unroll
        for (int j = 0; j < 4; j++) {
            o0[j] = fmaf(p0, v4[j], o0[j]);
            o1[j] = fmaf(p1, v4[j], o1[j]);
        }
    }
    {
        size_t d0 = (size_t)(w * 64 + ty2) * 256 + h * 32 + tx2 * 4;
        size_t d1 = (size_t)(w * 64 + ty2 + 32) * 256 + h * 32 + tx2 * 4;
        *(float4*)&g_attnout[d0] = make_float4(o0[0], o0[1], o0[2], o0[3]);
        *(float4*)&g_attnout[d1] = make_float4(o1[0], o1[1], o1[2], o1[3]);
    }
}

// ---------------- LayerNorm + residual ----------------
template <int WHICH>
__global__ void ln_add_kernel(const float* __restrict__ basep,
                              const float* __restrict__ g, const float* __restrict__ b,
                              float* __restrict__ outp) {
    const float* base = (WHICH == 0) ? basep : g_x1;
    const float* y = (WHICH == 0) ? g_projout : g_h2;
    float* out = (WHICH == 0) ? g_x1 : outp;

    int t = blockIdx.x;
    int c = threadIdx.x;
    size_t off = (size_t)t * 256 + c;
    float v = y[off];
    float s = v, s2 = v * v;
#pragma unroll
    for (int o = 16; o > 0; o >>= 1) {
        s += __shfl_xor_sync(0xffffffffu, s, o);
        s2 += __shfl_xor_sync(0xffffffffu, s2, o);
    }
    __shared__ float rs[8], rs2[8];
    int wid = c >> 5, lid = c & 31;
    if (lid == 0) { rs[wid] = s; rs2[wid] = s2; }
    __syncthreads();
    if (wid == 0) {
        float a = (lid < 8) ? rs[lid] : 0.0f;
        float a2 = (lid < 8) ? rs2[lid] : 0.0f;
#pragma unroll
        for (int o = 4; o > 0; o >>= 1) {
            a += __shfl_xor_sync(0xffffffffu, a, o);
            a2 += __shfl_xor_sync(0xffffffffu, a2, o);
        }
        if (lid == 0) { rs[0] = a; rs2[0] = a2; }
    }
    __syncthreads();
    float mu = rs[0] * (1.0f / 256.0f);
    float var = rs2[0] * (1.0f / 256.0f) - mu * mu;
    float inv = rsqrtf(var + 1e-5f);
    out[off] = base[off] + (v - mu) * inv * g[c] + b[c];
}

// ---------------- launch ----------------
extern "C" void kernel_launch(void* const* d_in, const int* in_sizes, int n_in,
                              void* d_out, int out_size) {
    const float* x = (const float*)d_in[0];
    const float* qkv_w = (const float*)d_in[1];
    const float* q_bias = (const float*)d_in[2];
    const float* v_bias = (const float*)d_in[3];
    const float* logit_scale = (const float*)d_in[4];
    const float* cpb_w1 = (const float*)d_in[5];
    const float* cpb_b1 = (const float*)d_in[6];
    const float* cpb_w2 = (const float*)d_in[7];
    const float* proj_w = (const float*)d_in[8];
    const float* proj_b = (const float*)d_in[9];
    const float* norm1_g = (const float*)d_in[10];
    const float* norm1_b = (const float*)d_in[11];
    const float* fc1_w = (const float*)d_in[12];
    const float* fc1_b = (const float*)d_in[13];
    const float* fc2_w = (const float*)d_in[14];
    const float* fc2_b = (const float*)d_in[15];
    const float* norm2_g = (const float*)d_in[16];
    const float* norm2_b = (const float*)d_in[17];
    float* out = (float*)d_out;

    cpb_kernel<<<225, 256>>>(cpb_w1, cpb_b1, cpb_w2);

    mma_gemm<0><<<dim3(1024, 6), 256>>>(x, qkv_w, q_bias, v_bias, 768, 256);
    attn_kernel<<<dim3(2048, 8), 256>>>(logit_scale);
    mma_gemm<1><<<dim3(1024, 2), 256>>>(nullptr, proj_w, proj_b, nullptr, 256, 256);
    ln_add_kernel<0><<<NTOK, 256>>>(x, norm1_g, norm1_b, nullptr);
    mma_gemm<2><<<dim3(1024, 8), 256>>>(nullptr, fc1_w, fc1_b, nullptr, 1024, 256);
    mma_gemm<3><<<dim3(1024, 2), 256>>>(nullptr, fc2_w, fc2_b, nullptr, 256, 1024);
    ln_add_kernel<1><<<NTOK, 256>>>(nullptr, norm2_g, norm2_b, out);

    (void)in_sizes; (void)n_in; (void)out_size;
}